// round 11
// baseline (speedup 1.0000x reference)
#include <cuda_runtime.h>
#include <cuda_bf16.h>

// patches: [B=2, N=49, C=8, P=256, P=256] fp32; out: [B, C, 1024, 1024] fp32.
// Inverse-gather, branch-free clamped 4-tile loads, {0,1}-weighted FMA,
// out = sum / (count + 1e-8), count in {1,2,4}.
//
// Row-walking layout: thread's w-column is FIXED (w4 = threadIdx.x), so all
// column-side coverage math is hoisted to the prologue. Each iteration the
// CTA processes one full (c,h) row: row-side coverage math is warp/CTA
// uniform (uniform-register pipe). Per-lane per-iteration work is ~2 adds +
// 8 independent float4 streaming loads + 2 stores.

namespace {
constexpr int NB = 2;
constexpr int NN = 49;
constexpr int NC = 8;
constexpr int PP = 256;
constexpr int HH = 1024;
constexpr int WW = 1024;
constexpr int TILES = 7;

constexpr int TOTAL_F4    = NB * NC * HH * WW / 4;  // 4,194,304
constexpr int HALF_F4     = TOTAL_F4 / 2;           // 2,097,152
constexpr int CH_F4       = PP * PP / 4;            // 16,384 f4 per channel
constexpr int BATCH_F4    = NN * NC * CH_F4;        // f4 per batch
constexpr int N_STRIDE_F4 = NC * CH_F4;             // f4 per tile index n
constexpr int ROWS        = NC * HH;                // 8192 (c,h) rows
constexpr int ROW_F4      = WW / 4;                 // 256 f4 per row
}

__global__ __launch_bounds__(256, 4) void patch_merge_rows(
    const float* __restrict__ patches, float* __restrict__ out)
{
    const float4* __restrict__ p4 = reinterpret_cast<const float4*>(patches);
    float4* __restrict__ o4 = reinterpret_cast<float4*>(out);

    // ---- Per-thread column-side constants (computed once) ----
    const int w4 = threadIdx.x;          // 0..255
    const int w  = w4 << 2;              // 0..1020
    const int tww = w >> 7;
    const int tw0 = tww - 1 < 0 ? 0 : tww - 1;
    const int tw1 = tww > TILES - 1 ? TILES - 1 : tww;
    const float wc = (tw1 != tw0) ? 1.f : 0.f;
    const int pw0f4 = (w - (tw0 << 7)) >> 2;      // 0..63
    const int pw1f4 = (w - (tw1 << 7)) >> 2;
    // column part of tile offsets (f4): tile n = th*7 + tw
    const int colOff0 = tw0 * N_STRIDE_F4 + pw0f4;
    const int colOff1 = tw1 * N_STRIDE_F4 + pw1f4;

    // ---- Row loop: one (c,h) row per CTA per iteration ----
    #pragma unroll 2
    for (int r = blockIdx.x; r < ROWS; r += gridDim.x) {
        // Uniform across the CTA:
        int c = r >> 10;                 // 0..7
        int h = r & (HH - 1);            // 0..1023
        int thh = h >> 7;
        int th0 = thh - 1 < 0 ? 0 : thh - 1;
        int th1 = thh > TILES - 1 ? TILES - 1 : thh;
        float wr = (th1 != th0) ? 1.f : 0.f;
        int rowOff0 = (th0 * TILES) * N_STRIDE_F4 + ((h - (th0 << 7)) << 6);
        int rowOff1 = (th1 * TILES) * N_STRIDE_F4 + ((h - (th1 << 7)) << 6);
        int plane0 = c * CH_F4;                  // b = 0
        int plane1 = plane0 + BATCH_F4;          // b = 1

        // Per-lane: combine row(uniform) + col(thread-invariant) parts.
        int s00 = rowOff0 + colOff0;
        int s01 = rowOff0 + colOff1;
        int s10 = rowOff1 + colOff0;
        int s11 = rowOff1 + colOff1;

        float4 v0 = __ldcs(p4 + plane0 + s00);
        float4 v1 = __ldcs(p4 + plane0 + s01);
        float4 v2 = __ldcs(p4 + plane0 + s10);
        float4 v3 = __ldcs(p4 + plane0 + s11);
        float4 u0 = __ldcs(p4 + plane1 + s00);
        float4 u1 = __ldcs(p4 + plane1 + s01);
        float4 u2 = __ldcs(p4 + plane1 + s10);
        float4 u3 = __ldcs(p4 + plane1 + s11);

        float w01 = wc, w10 = wr, w11 = wr * wc;
        float cnt = (1.f + wr) * (1.f + wc);     // exactly 1, 2, or 4
        float inv = 1.f / (cnt + 1e-8f);

        int oidx = r * ROW_F4 + w4;              // f4 index in b=0 half

        float4 a;
        a.x = (v0.x + w01 * v1.x + w10 * v2.x + w11 * v3.x) * inv;
        a.y = (v0.y + w01 * v1.y + w10 * v2.y + w11 * v3.y) * inv;
        a.z = (v0.z + w01 * v1.z + w10 * v2.z + w11 * v3.z) * inv;
        a.w = (v0.w + w01 * v1.w + w10 * v2.w + w11 * v3.w) * inv;
        o4[oidx] = a;

        float4 bq;
        bq.x = (u0.x + w01 * u1.x + w10 * u2.x + w11 * u3.x) * inv;
        bq.y = (u0.y + w01 * u1.y + w10 * u2.y + w11 * u3.y) * inv;
        bq.z = (u0.z + w01 * u1.z + w10 * u2.z + w11 * u3.z) * inv;
        bq.w = (u0.w + w01 * u1.w + w10 * u2.w + w11 * u3.w) * inv;
        o4[oidx + HALF_F4] = bq;
    }
}

extern "C" void kernel_launch(void* const* d_in, const int* in_sizes, int n_in,
                              void* d_out, int out_size)
{
    const float* patches = (const float*)d_in[0];
    float* out = (float*)d_out;

    int dev = 0, sms = 148, maxBlk = 0;
    cudaGetDevice(&dev);
    cudaDeviceGetAttribute(&sms, cudaDevAttrMultiProcessorCount, dev);
    cudaOccupancyMaxActiveBlocksPerMultiprocessor(
        &maxBlk, patch_merge_rows, 256, 0);
    if (maxBlk < 1) maxBlk = 4;
    int grid = sms * maxBlk;                 // single balanced wave
    if (grid > ROWS) grid = ROWS;

    patch_merge_rows<<<grid, 256>>>(patches, out);
}